// round 8
// baseline (speedup 1.0000x reference)
#include <cuda_runtime.h>
#include <cstdint>

#define Bn 64
#define Tn 2048
#define In 128
#define Hn 256
#define THREADS 256
#define CLU 8
#define NCOL 32
#define NBAT 4
#define RPAD 260

typedef unsigned long long u64;
typedef uint32_t u32;

__device__ __align__(256) u64 g_xT2[(size_t)Tn*In*Bn];  // x transposed, dup'd {v,v}
__device__ __align__(256) u64 g_wX[In*Hn];              // layer0 x-weights {wc,wa}

__device__ __forceinline__ void fma2(u64&d,u64 a,u64 b){asm("fma.rn.f32x2 %0,%1,%2,%0;":"+l"(d):"l"(a),"l"(b));}
__device__ __forceinline__ u64 add2(u64 a,u64 b){u64 d;asm("add.rn.f32x2 %0,%1,%2;":"=l"(d):"l"(a),"l"(b));return d;}
__device__ __forceinline__ u64 dup2(float f){u64 d;asm("mov.b64 %0,{%1,%1};":"=l"(d):"f"(f));return d;}
__device__ __forceinline__ u64 pack2(float l,float h){u64 d;asm("mov.b64 %0,{%1,%2};":"=l"(d):"f"(l),"f"(h));return d;}
__device__ __forceinline__ float lo2(u64 v){return __uint_as_float((unsigned)v);}
__device__ __forceinline__ float hi2(u64 v){return __uint_as_float((unsigned)(v>>32));}
__device__ __forceinline__ u32 s2u(const void*p){u32 a;asm("{.reg .u64 t; cvta.to.shared.u64 t,%1; cvt.u32.u64 %0,t;}":"=r"(a):"l"(p));return a;}

__device__ __forceinline__ void mb_init(u32 a,u32 c){asm volatile("mbarrier.init.shared.b64 [%0],%1;"::"r"(a),"r"(c):"memory");}
__device__ __forceinline__ void mb_arrive(u32 a){asm volatile("mbarrier.arrive.shared.b64 _,[%0];"::"r"(a):"memory");}
__device__ __forceinline__ void mb_arrive_rank(u32 a,u32 r){
  asm volatile("{\n\t.reg .b32 ra;\n\tmapa.shared::cluster.u32 ra,%0,%1;\n\tmbarrier.arrive.shared::cluster.b64 _,[ra];\n\t}"::"r"(a),"r"(r):"memory");
}
__device__ __forceinline__ void mb_wait(u32 a,u32 p){
  asm volatile("{\n\t.reg .pred P1;\n\tWL_%=:\n\tmbarrier.try_wait.parity.acquire.cta.shared::cta.b64 P1,[%0],%1,0x989680;\n\t@P1 bra.uni WD_%=;\n\tbra.uni WL_%=;\n\tWD_%=:\n\t}"::"r"(a),"r"(p):"memory");
}
__device__ __forceinline__ void stc_u64(u32 a,u32 r,u64 v){
  asm volatile("{\n\t.reg .b32 ra;\n\tmapa.shared::cluster.u32 ra,%0,%1;\n\tst.shared::cluster.u64 [ra],%2;\n\t}"::"r"(a),"r"(r),"l"(v):"memory");
}
__device__ __forceinline__ void fence_cl(){asm volatile("fence.acq_rel.cluster;":::"memory");}

__global__ void prep_kernel(const float* __restrict__ x,const float* __restrict__ Wih0,const float* __restrict__ Wax0){
  __shared__ float s[In][65];
  const int t=blockIdx.x, tid=threadIdx.x;
  for(int i=tid;i<Bn*In;i+=THREADS){int b=i>>7,k=i&(In-1); s[k][b]=x[((size_t)b*Tn+t)*In+k];}
  __syncthreads();
  for(int i=tid;i<In*Bn;i+=THREADS){int k=i>>6,b=i&(Bn-1); g_xT2[((size_t)t*In+k)*Bn+b]=dup2(s[k][b]);}
  if(t<In) for(int c=tid;c<Hn;c+=THREADS) g_wX[t*Hn+c]=pack2(Wih0[t*Hn+c],Wax0[t*Hn+c]);
}

__global__ void __launch_bounds__(THREADS,1) __cluster_dims__(CLU,1,1)
rnn_kernel(const float* __restrict__ Whh0,const float* __restrict__ bh0,
           const float* __restrict__ Wah0,const float* __restrict__ ba0,
           const float* __restrict__ Wih1,const float* __restrict__ Whh1,
           const float* __restrict__ bh1, const float* __restrict__ Wax1,
           const float* __restrict__ Wah1,const float* __restrict__ ba1,
           float* __restrict__ out)
{
  extern __shared__ u64 sm[];
  u64* wAs=sm;                  // [256][32] layer0 h-weights
  u64* wBs=wAs+256*NCOL;        // [512][32] layer1 weights
  u64* sh0=wBs+512*NCOL;        // [256][4] dup'd h0[t] (full H, our 4 batches)
  u64* sh1=sh0+Hn*NBAT;         // [256][4] dup'd h1[t-1]
  u64* red=sh1+Hn*NBAT;         // [8][RPAD]
  u64* biasA=red+8*RPAD;        // [32]
  u64* biasB=biasA+NCOL;        // [32]
  __shared__ u64 s_mb[3];

  const int tid=threadIdx.x;
  u32 rank; asm("mov.u32 %0,%%cluster_ctarank;":"=r"(rank));
  const int col0=rank*NCOL;
  const int bbase=(blockIdx.x>>3)*NBAT;
  const u32 rd_a=s2u(&s_mb[0]), lf_a=s2u(&s_mb[1]), gf_a=s2u(&s_mb[2]);
  const u32 sh0_a=s2u(sh0), sh1_a=s2u(sh1);

  for(int i=tid;i<256*NCOL;i+=THREADS){int k=i>>5,C=col0+(i&31); wAs[i]=pack2(Whh0[k*Hn+C],Wah0[k*Hn+C]);}
  for(int i=tid;i<512*NCOL;i+=THREADS){int k=i>>5,C=col0+(i&31);
    wBs[i]=(k<Hn)?pack2(Wih1[k*Hn+C],Wax1[k*Hn+C]):pack2(Whh1[(k-Hn)*Hn+C],Wah1[(k-Hn)*Hn+C]);}
  if(tid<NCOL){biasA[tid]=pack2(bh0[col0+tid],ba0[col0+tid]);biasB[tid]=pack2(bh1[col0+tid],ba1[col0+tid]);}
  for(int i=tid;i<Hn*NBAT;i+=THREADS){sh0[i]=0ull;sh1[i]=0ull;}
  if(tid==0){mb_init(rd_a,CLU);mb_init(lf_a,THREADS);mb_init(gf_a,CLU);}
  __syncthreads();
  asm volatile("barrier.cluster.arrive.aligned;":::"memory");
  asm volatile("barrier.cluster.wait.aligned;":::"memory");

  const int w=tid>>5, ln=tid&31;
  const int bp=ln>>4, cp=ln&15;       // batch-pair 0..1, col-pair 0..15
  const int kh=w*32, kx=w*16;
  const int ph=tid>>7, cell=tid&127;  // epilogue: phase, (col,batch) cell
  const int oc=cell>>2, ob=cell&3;
  const int OC=col0+oc, OB=bbase+ob;
  float h0prev=0.f, h1prev=0.f;

  auto xpart=[&](int s,u64&a0,u64&a1,u64&a2,u64&a3){
    const u64* xp=g_xT2+((size_t)s*In+kx)*Bn+bbase+2*bp;
    const u64* wp=g_wX+(size_t)kx*Hn+col0+2*cp;
#pragma unroll
    for(int k=0;k<16;k++){
      ulonglong2 sv=*(const ulonglong2*)(xp+(size_t)k*Bn);
      ulonglong2 wv=*(const ulonglong2*)(wp+(size_t)k*Hn);
      fma2(a0,sv.x,wv.x); fma2(a1,sv.x,wv.y);
      fma2(a2,sv.y,wv.x); fma2(a3,sv.y,wv.y);
    }
  };

  u64 xn0=0,xn1=0,xn2=0,xn3=0;
  xpart(0,xn0,xn1,xn2,xn3);

  for(int t=-1;t<Tn;t++){
    const int s=t+1;
    const bool doA=(s<Tn), doB=(t>=0);
    const u32 par=(u32)(s&1);

    // phase A: x-part (preloaded) + h0[t] x wA
    u64 aA00=xn0,aA01=xn1,aA10=xn2,aA11=xn3;
    {
      const u64* sp=sh0+kh*NBAT+2*bp;
      const u64* wp=wAs+kh*NCOL+2*cp;
#pragma unroll 8
      for(int i=0;i<32;i++){
        ulonglong2 sv=*(const ulonglong2*)(sp+i*NBAT);
        ulonglong2 wv=*(const ulonglong2*)(wp+i*NCOL);
        fma2(aA00,sv.x,wv.x); fma2(aA01,sv.x,wv.y);
        fma2(aA10,sv.y,wv.x); fma2(aA11,sv.y,wv.y);
      }
    }
    // phase B: h0[t] x wB1 + h1[t-1] x wB2
    u64 aB00=0,aB01=0,aB10=0,aB11=0;
    {
      const u64* s0=sh0+kh*NBAT+2*bp;
      const u64* w1=wBs+kh*NCOL+2*cp;
      const u64* s1=sh1+kh*NBAT+2*bp;
      const u64* w2=wBs+(Hn+kh)*NCOL+2*cp;
#pragma unroll 8
      for(int i=0;i<32;i++){
        ulonglong2 sv=*(const ulonglong2*)(s0+i*NBAT);
        ulonglong2 wv=*(const ulonglong2*)(w1+i*NCOL);
        fma2(aB00,sv.x,wv.x); fma2(aB01,sv.x,wv.y);
        fma2(aB10,sv.y,wv.x); fma2(aB11,sv.y,wv.y);
        sv=*(const ulonglong2*)(s1+i*NBAT);
        wv=*(const ulonglong2*)(w2+i*NCOL);
        fma2(aB00,sv.x,wv.x); fma2(aB01,sv.x,wv.y);
        fma2(aB10,sv.y,wv.x); fma2(aB11,sv.y,wv.y);
      }
    }
    // stage partials: cell=(c*4+b), pairs {b even, b odd}
    {
      u64* rr=red+w*RPAD;
      *(ulonglong2*)(rr+8*cp+2*bp)      =make_ulonglong2(aA00,aA10);
      *(ulonglong2*)(rr+8*cp+4+2*bp)    =make_ulonglong2(aA01,aA11);
      *(ulonglong2*)(rr+128+8*cp+2*bp)  =make_ulonglong2(aB00,aB10);
      *(ulonglong2*)(rr+128+8*cp+4+2*bp)=make_ulonglong2(aB01,aB11);
    }
    __syncthreads();   // all sh reads in this CTA complete
    if(tid==0){
#pragma unroll
      for(u32 r=0;r<CLU;r++) mb_arrive_rank(rd_a,r);
    }
    // reduce + epilogue
    const bool live = ph ? doB : doA;
    float hn=0.f;
    {
      u64 acc = ph ? biasB[oc] : biasA[oc];
#pragma unroll
      for(int ww=0;ww<8;ww++) acc=add2(acc,red[ww*RPAD+ph*128+cell]);
      if(live){
        float cnd=lo2(acc), alp=hi2(acc);
        float tv=1.f-__fdividef(2.f,__expf(2.f*cnd)+1.f);
        float sg=__fdividef(1.f,1.f+__expf(-alp));
        float hp = ph ? h1prev : h0prev;
        hn=fmaf(sg,tv-hp,hp);
        if(ph) h1prev=hn; else h0prev=hn;
      }
    }
    mb_wait(rd_a,par);                  // all cluster CTAs done reading sh
    if(live){
      u64 hd=dup2(hn);
      u32 dst=(ph?sh1_a:sh0_a)+(u32)(OC*NBAT+ob)*8u;
#pragma unroll
      for(u32 r=0;r<CLU;r++) stc_u64(dst,r,hd);
    }
    fence_cl();
    mb_arrive(lf_a);                    // local: my pushes released
    if(ph && doB) out[((size_t)OB*Tn+t)*Hn+OC]=hn;
    xn0=0;xn1=0;xn2=0;xn3=0;
    if(t+2<Tn) xpart(t+2,xn0,xn1,xn2,xn3);
    if(tid==0){
      mb_wait(lf_a,par);
      fence_cl();
#pragma unroll
      for(u32 r=0;r<CLU;r++) mb_arrive_rank(gf_a,r);
    }
    mb_wait(gf_a,par);                  // all cluster pushes visible
    fence_cl();
  }

  const size_t OFF=(size_t)Bn*Tn*Hn;
  if(ph==0) out[OFF+(size_t)OB*Hn+OC]=h0prev;
  else      out[OFF+(size_t)Bn*Hn+(size_t)OB*Hn+OC]=h1prev;
}

extern "C" void kernel_launch(void* const* d_in,const int* in_sizes,int n_in,
                              void* d_out,int out_size){
  const float* x   =(const float*)d_in[0];
  const float* Wih0=(const float*)d_in[1];
  const float* Whh0=(const float*)d_in[2];
  const float* bh0 =(const float*)d_in[3];
  const float* Wax0=(const float*)d_in[4];
  const float* Wah0=(const float*)d_in[5];
  const float* ba0 =(const float*)d_in[6];
  const float* Wih1=(const float*)d_in[7];
  const float* Whh1=(const float*)d_in[8];
  const float* bh1 =(const float*)d_in[9];
  const float* Wax1=(const float*)d_in[10];
  const float* Wah1=(const float*)d_in[11];
  const float* ba1 =(const float*)d_in[12];
  float* out=(float*)d_out;

  const int smem=(256*NCOL+512*NCOL+2*Hn*NBAT+8*RPAD+2*NCOL)*8;
  cudaFuncSetAttribute(rnn_kernel,cudaFuncAttributeMaxDynamicSharedMemorySize,smem);
  prep_kernel<<<Tn,THREADS>>>(x,Wih0,Wax0);
  rnn_kernel<<<128,THREADS,smem>>>(Whh0,bh0,Wah0,ba0,Wih1,Whh1,bh1,Wax1,Wah1,ba1,out);
}

// round 9
// speedup vs baseline: 1.9604x; 1.9604x over previous
#include <cuda_runtime.h>

#define Bn 64
#define Tn 2048
#define In 128
#define Hn 256
#define THREADS 512
#define PT 256
#define NCOL 16
#define NBAT 8
#define NCG  (Hn / NCOL)        // 16 col-groups (one sync domain)
#define NBG  (Bn / NBAT)        // 8 batch-groups (independent domains)
#define GCTA (NCG * NBG)
#define KA 384
#define KB 512
#define RSTRIDE 10

typedef unsigned long long u64;

__device__ __align__(256) u64   g_xT2[(size_t)Tn * In * Bn];  // x dup'd {v,v}: [t][k][b]
__device__ __align__(256) float g_h0[2 * Hn * Bn];
__device__ __align__(256) float g_h1[2 * Hn * Bn];
__device__ __align__(128) unsigned g_count[NBG * 32];         // per-group counters, 128B apart

__device__ __forceinline__ void fma2(u64 &d, u64 a, u64 b) {
    asm("fma.rn.f32x2 %0, %1, %2, %0;" : "+l"(d) : "l"(a), "l"(b));
}
__device__ __forceinline__ u64 add2(u64 a, u64 b) {
    u64 d; asm("add.rn.f32x2 %0, %1, %2;" : "=l"(d) : "l"(a), "l"(b)); return d;
}
__device__ __forceinline__ u64 dup2(float f) {
    u64 d; asm("mov.b64 %0, {%1, %1};" : "=l"(d) : "f"(f)); return d;
}
__device__ __forceinline__ u64 pack2(float lo, float hi) {
    u64 d; asm("mov.b64 %0, {%1, %2};" : "=l"(d) : "f"(lo), "f"(hi)); return d;
}
__device__ __forceinline__ float lo2(u64 v) { return __uint_as_float((unsigned)(v & 0xffffffffull)); }
__device__ __forceinline__ float hi2(u64 v) { return __uint_as_float((unsigned)(v >> 32)); }

__device__ __forceinline__ void ldcg2(const u64* p, u64 &a, u64 &b) {
    asm volatile("ld.global.cg.v2.u64 {%0, %1}, [%2];" : "=l"(a), "=l"(b) : "l"(p));
}
__device__ __forceinline__ float4 ldcgf4(const float* p) {
    float4 v;
    asm volatile("ld.global.cg.v4.f32 {%0, %1, %2, %3}, [%4];"
                 : "=f"(v.x), "=f"(v.y), "=f"(v.z), "=f"(v.w) : "l"(p));
    return v;
}
__device__ __forceinline__ void stcgf(float* p, float v) {
    asm volatile("st.global.cg.f32 [%0], %1;" :: "l"(p), "f"(v) : "memory");
}

// per-group barrier: entry sync + tid0 release-add, then ALL threads acquire-poll.
__device__ __forceinline__ void group_barrier(unsigned* ctr, unsigned target) {
    __syncthreads();
    if (threadIdx.x == 0) {
        unsigned old;
        asm volatile("atom.release.gpu.global.add.u32 %0, [%1], 1;"
                     : "=r"(old) : "l"(ctr) : "memory");
    }
    unsigned v;
    do {
        asm volatile("ld.acquire.gpu.global.u32 %0, [%1];" : "=r"(v) : "l"(ctr) : "memory");
    } while (v < target);
}

__global__ void prep_kernel(const float* __restrict__ x) {
    __shared__ float s[In][65];
    const int t = blockIdx.x;
    const int tid = threadIdx.x;
    for (int idx = tid; idx < Bn * In; idx += PT) {
        int b = idx >> 7, i = idx & (In - 1);
        s[i][b] = x[((size_t)b * Tn + t) * In + i];
    }
    __syncthreads();
    for (int idx = tid; idx < In * Bn; idx += PT) {
        int i = idx >> 6, b = idx & (Bn - 1);
        g_xT2[((size_t)t * In + i) * Bn + b] = dup2(s[i][b]);
    }
    if (t == 0 && tid < NBG) g_count[tid * 32] = 0u;
    if (t < 2) {
        for (int i = tid; i < Hn * Bn; i += PT) {
            g_h0[t * Hn * Bn + i] = 0.0f;
            g_h1[t * Hn * Bn + i] = 0.0f;
        }
    }
}

__global__ void __launch_bounds__(THREADS, 1) rnn_kernel(
    const float* __restrict__ Wih0, const float* __restrict__ Whh0,
    const float* __restrict__ bh0,  const float* __restrict__ Wax0,
    const float* __restrict__ Wah0, const float* __restrict__ ba0,
    const float* __restrict__ Wih1, const float* __restrict__ Whh1,
    const float* __restrict__ bh1,  const float* __restrict__ Wax1,
    const float* __restrict__ Wah1, const float* __restrict__ ba1,
    float* __restrict__ out)
{
    extern __shared__ u64 sm[];
    u64* wAs   = sm;
    u64* wBs   = wAs + KA * NCOL;
    u64* sh0   = wBs + KB * NCOL;
    u64* sh1   = sh0 + Hn * NBAT;
    u64* red   = sh1 + Hn * NBAT;
    u64* sbias = red + THREADS * RSTRIDE;

    const int tid  = threadIdx.x;
    const int cg   = blockIdx.x & (NCG - 1);
    const int bg   = blockIdx.x >> 4;
    const int col0 = cg * NCOL;
    const int b0g  = bg * NBAT;
    unsigned* ctr  = &g_count[bg * 32];

    for (int idx = tid; idx < KA * NCOL; idx += THREADS) {
        int k = idx >> 4, c = idx & 15, C = col0 + c;
        float wc = (k < In) ? Wih0[k * Hn + C] : Whh0[(k - In) * Hn + C];
        float wa = (k < In) ? Wax0[k * Hn + C] : Wah0[(k - In) * Hn + C];
        wAs[idx] = pack2(wc, wa);
    }
    for (int idx = tid; idx < KB * NCOL; idx += THREADS) {
        int k = idx >> 4, c = idx & 15, C = col0 + c;
        float wc = (k < Hn) ? Wih1[k * Hn + C] : Whh1[(k - Hn) * Hn + C];
        float wa = (k < Hn) ? Wax1[k * Hn + C] : Wah1[(k - Hn) * Hn + C];
        wBs[idx] = pack2(wc, wa);
    }
    if (tid < 2 * NCOL) {
        int c = tid & 15, l = tid >> 4;
        sbias[tid] = l ? pack2(bh1[col0 + c], ba1[col0 + c])
                       : pack2(bh0[col0 + c], ba0[col0 + c]);
    }
    __syncthreads();

    const int w  = tid >> 5;
    const int ln = tid & 31;
    const int bp = ln >> 3;
    const int cp = ln & 7;
    const int b0 = b0g + bp * 2;
    const int kx = w * 8;
    const int kh = w * 16;

    const int sk = tid >> 1;
    const int sb = (tid & 1) * 4;

    const int rp   = tid >> 7;
    const int cell = tid & 127;
    const int rb   = cell >> 4;
    const int rc   = cell & 15;
    const int ridx = (rb >> 1) * 8 + (rc >> 1);
    const int raid = rp * 4 + (rb & 1) * 2 + (rc & 1);
    float hprev = 0.0f;

    auto xpart = [&](int s, u64 &a00, u64 &a01, u64 &a10, u64 &a11) {
        const u64* xp = g_xT2 + ((size_t)s * In + kx) * Bn + b0;
        const u64* wp = wAs + kx * NCOL + cp * 2;
#pragma unroll
        for (int k = 0; k < 8; k++) {
            u64 s0, s1; ldcg2(xp + (size_t)k * Bn, s0, s1);
            ulonglong2 wv = *(const ulonglong2*)(wp + k * NCOL);
            fma2(a00, s0, wv.x); fma2(a01, s0, wv.y);
            fma2(a10, s1, wv.x); fma2(a11, s1, wv.y);
        }
    };

    u64 x00 = 0, x01 = 0, x10 = 0, x11 = 0;
    xpart(0, x00, x01, x10, x11);

    unsigned bar = 1;

    for (int t = -1; t < Tn; t++) {
        const int s = t + 1;
        const bool doA = (s < Tn);
        const bool doB = (t >= 0);

        {
            float4 v0 = ldcgf4(&g_h0[((t & 1) * Hn + sk) * Bn + b0g + sb]);
            float4 v1 = ldcgf4(&g_h1[((((t + 1) & 1)) * Hn + sk) * Bn + b0g + sb]);
            u64* d0 = sh0 + sk * NBAT + sb;
            u64* d1 = sh1 + sk * NBAT + sb;
            d0[0] = dup2(v0.x); d0[1] = dup2(v0.y); d0[2] = dup2(v0.z); d0[3] = dup2(v0.w);
            d1[0] = dup2(v1.x); d1[1] = dup2(v1.y); d1[2] = dup2(v1.z); d1[3] = dup2(v1.w);
        }
        __syncthreads();

        u64 aA00 = x00, aA01 = x01, aA10 = x10, aA11 = x11;
        u64 aB00 = 0, aB01 = 0, aB10 = 0, aB11 = 0;

        {
            const u64* hp  = sh0 + kh * NBAT + bp * 2;
            const u64* wpa = wAs + (In + kh) * NCOL + cp * 2;
            const u64* wpb = wBs + kh * NCOL + cp * 2;
            if (doA && doB) {
#pragma unroll 8
                for (int k = 0; k < 16; k++) {
                    ulonglong2 sv = *(const ulonglong2*)(hp + k * NBAT);
                    ulonglong2 wa = *(const ulonglong2*)(wpa + k * NCOL);
                    ulonglong2 wb = *(const ulonglong2*)(wpb + k * NCOL);
                    fma2(aA00, sv.x, wa.x); fma2(aA01, sv.x, wa.y);
                    fma2(aA10, sv.y, wa.x); fma2(aA11, sv.y, wa.y);
                    fma2(aB00, sv.x, wb.x); fma2(aB01, sv.x, wb.y);
                    fma2(aB10, sv.y, wb.x); fma2(aB11, sv.y, wb.y);
                }
            } else if (doA) {
#pragma unroll 8
                for (int k = 0; k < 16; k++) {
                    ulonglong2 sv = *(const ulonglong2*)(hp + k * NBAT);
                    ulonglong2 wa = *(const ulonglong2*)(wpa + k * NCOL);
                    fma2(aA00, sv.x, wa.x); fma2(aA01, sv.x, wa.y);
                    fma2(aA10, sv.y, wa.x); fma2(aA11, sv.y, wa.y);
                }
            } else {
#pragma unroll 8
                for (int k = 0; k < 16; k++) {
                    ulonglong2 sv = *(const ulonglong2*)(hp + k * NBAT);
                    ulonglong2 wb = *(const ulonglong2*)(wpb + k * NCOL);
                    fma2(aB00, sv.x, wb.x); fma2(aB01, sv.x, wb.y);
                    fma2(aB10, sv.y, wb.x); fma2(aB11, sv.y, wb.y);
                }
            }
        }

        if (doB) {
            const u64* hp = sh1 + kh * NBAT + bp * 2;
            const u64* wp = wBs + (Hn + kh) * NCOL + cp * 2;
#pragma unroll 8
            for (int k = 0; k < 16; k++) {
                ulonglong2 sv = *(const ulonglong2*)(hp + k * NBAT);
                ulonglong2 wv = *(const ulonglong2*)(wp + k * NCOL);
                fma2(aB00, sv.x, wv.x); fma2(aB01, sv.x, wv.y);
                fma2(aB10, sv.y, wv.x); fma2(aB11, sv.y, wv.y);
            }
        }

        {
            u64* rr = red + tid * RSTRIDE;
            *(ulonglong2*)(rr + 0) = make_ulonglong2(aA00, aA01);
            *(ulonglong2*)(rr + 2) = make_ulonglong2(aA10, aA11);
            *(ulonglong2*)(rr + 4) = make_ulonglong2(aB00, aB01);
            *(ulonglong2*)(rr + 6) = make_ulonglong2(aB10, aB11);
        }
        __syncthreads();

        if (tid < 256 && (rp ? doB : doA)) {
            u64 acc0 = sbias[rp * NCOL + rc];
            u64 acc1 = 0;
#pragma unroll
            for (int ww = 0; ww < 16; ww += 2) {
                acc0 = add2(acc0, red[(ww * 32 + ridx) * RSTRIDE + raid]);
                acc1 = add2(acc1, red[((ww + 1) * 32 + ridx) * RSTRIDE + raid]);
            }
            u64 acc = add2(acc0, acc1);
            float cnd = fmaxf(lo2(acc), -15.0f);
            float alp = fmaxf(hi2(acc), -30.0f);
            // fused blend: 2 ex2 + 1 rcp
            float v = __expf(-2.0f * cnd);
            float u = __expf(-alp);
            float t2 = 1.0f + v;
            float num = __fmaf_rn(u * hprev, t2, 1.0f - v);
            float den = (1.0f + u) * t2;
            float hn = __fdividef(num, den);
            hprev = hn;
            const int C = col0 + rc, B = b0g + rb;
            if (rp == 0) {
                stcgf(&g_h0[((s & 1) * Hn + C) * Bn + B], hn);
            } else {
                stcgf(&g_h1[((t & 1) * Hn + C) * Bn + B], hn);
                out[((size_t)B * Tn + t) * Hn + C] = hn;
            }
        }

        x00 = 0; x01 = 0; x10 = 0; x11 = 0;
        if (t + 2 < Tn) xpart(t + 2, x00, x01, x10, x11);

        group_barrier(ctr, NCG * bar); bar++;
    }

    if (tid < 256) {
        const int l = tid >> 7, r = tid & 127;
        const int b = r >> 4, c = r & 15;
        const int C = col0 + c, B = b0g + b;
        const float* src = l ? &g_h1[(1 * Hn + C) * Bn + B]
                             : &g_h0[(1 * Hn + C) * Bn + B];
        out[(size_t)Bn * Tn * Hn + (size_t)l * Bn * Hn + (size_t)B * Hn + C] = *src;
    }
}

extern "C" void kernel_launch(void* const* d_in, const int* in_sizes, int n_in,
                              void* d_out, int out_size) {
    const float* x    = (const float*)d_in[0];
    const float* Wih0 = (const float*)d_in[1];
    const float* Whh0 = (const float*)d_in[2];
    const float* bh0  = (const float*)d_in[3];
    const float* Wax0 = (const float*)d_in[4];
    const float* Wah0 = (const float*)d_in[5];
    const float* ba0  = (const float*)d_in[6];
    const float* Wih1 = (const float*)d_in[7];
    const float* Whh1 = (const float*)d_in[8];
    const float* bh1  = (const float*)d_in[9];
    const float* Wax1 = (const float*)d_in[10];
    const float* Wah1 = (const float*)d_in[11];
    const float* ba1  = (const float*)d_in[12];
    float* out = (float*)d_out;

    const int smem = (KA + KB) * NCOL * 8
                   + 2 * Hn * NBAT * 8
                   + THREADS * RSTRIDE * 8
                   + 2 * NCOL * 8;
    cudaFuncSetAttribute(rnn_kernel, cudaFuncAttributeMaxDynamicSharedMemorySize, smem);

    prep_kernel<<<Tn, PT>>>(x);
    rnn_kernel<<<GCTA, THREADS, smem>>>(
        Wih0, Whh0, bh0, Wax0, Wah0, ba0,
        Wih1, Whh1, bh1, Wax1, Wah1, ba1,
        out);
}

// round 10
// speedup vs baseline: 2.0951x; 1.0687x over previous
#include <cuda_runtime.h>
#include <cstdint>

#define Bn 64
#define Tn 2048
#define In 128
#define Hn 256
#define THREADS 512
#define PT 256
#define NCOL 16
#define NBAT 8
#define NCG  16
#define NBG  8
#define GCTA 128
#define KA 384
#define KB 512
#define RS 6                    // reduction stride (u64), 16B-aligned

typedef unsigned long long u64;
typedef uint32_t u32;

// ---------------- device scratch ----------------
__device__ __align__(256) u64   g_xT2[(size_t)Tn * In * Bn];  // x dup'd {v,v}: [t][k][b]
__device__ __align__(256) float g_h0[2 * Hn * Bn];            // [buf][k][b]
__device__ __align__(256) float g_h1[2 * Hn * Bn];
__device__ __align__(128) unsigned g_ctrA[NBG * 32];          // per-group A counters
__device__ __align__(128) unsigned g_ctrB[NBG * 32];          // per-group B counters

// ---------------- packed f32x2 helpers ----------------
__device__ __forceinline__ void fma2(u64 &d, u64 a, u64 b) {
    asm("fma.rn.f32x2 %0, %1, %2, %0;" : "+l"(d) : "l"(a), "l"(b));
}
__device__ __forceinline__ u64 add2(u64 a, u64 b) {
    u64 d; asm("add.rn.f32x2 %0, %1, %2;" : "=l"(d) : "l"(a), "l"(b)); return d;
}
__device__ __forceinline__ u64 dup2(float f) {
    u64 d; asm("mov.b64 %0, {%1, %1};" : "=l"(d) : "f"(f)); return d;
}
__device__ __forceinline__ u64 pack2(float lo, float hi) {
    u64 d; asm("mov.b64 %0, {%1, %2};" : "=l"(d) : "f"(lo), "f"(hi)); return d;
}
__device__ __forceinline__ float lo2(u64 v) { return __uint_as_float((unsigned)(v & 0xffffffffull)); }
__device__ __forceinline__ float hi2(u64 v) { return __uint_as_float((unsigned)(v >> 32)); }

__device__ __forceinline__ void ldcg2(const u64* p, u64 &a, u64 &b) {
    asm volatile("ld.global.cg.v2.u64 {%0, %1}, [%2];" : "=l"(a), "=l"(b) : "l"(p));
}
__device__ __forceinline__ float4 ldcgf4(const float* p) {
    float4 v;
    asm volatile("ld.global.cg.v4.f32 {%0, %1, %2, %3}, [%4];"
                 : "=f"(v.x), "=f"(v.y), "=f"(v.z), "=f"(v.w) : "l"(p));
    return v;
}
__device__ __forceinline__ void stcgf(float* p, float v) {
    asm volatile("st.global.cg.f32 [%0], %1;" :: "l"(p), "f"(v) : "memory");
}

// global release-arrive / acquire-poll (monotonic counters)
__device__ __forceinline__ void g_arrive(unsigned* c) {
    unsigned old;
    asm volatile("atom.release.gpu.global.add.u32 %0, [%1], 1;" : "=r"(old) : "l"(c) : "memory");
}
__device__ __forceinline__ void g_poll(unsigned* c, int tgt) {
    if (tgt <= 0) return;
    int v;
    do { asm volatile("ld.acquire.gpu.global.u32 %0, [%1];" : "=r"(v) : "l"(c) : "memory"); } while (v < tgt);
}
// smem mailbox: volatile poll + fences
__device__ __forceinline__ void s_poll(volatile unsigned* c, int tgt) {
    if (tgt <= 0) return;
    while ((int)(*c) < tgt) { }
    __threadfence_block();
}
__device__ __forceinline__ void nbar(int id) {
    asm volatile("bar.sync %0, 256;" :: "r"(id) : "memory");
}

// fused blend: h' = sg(a)*tanh(c) + (1-sg(a))*hp, 2 ex2 + 1 rcp
__device__ __forceinline__ float blend(u64 acc, float hp) {
    float cnd = fmaxf(lo2(acc), -15.0f);
    float alp = fmaxf(hi2(acc), -30.0f);
    float v = __expf(-2.0f * cnd);
    float u = __expf(-alp);
    float t2 = 1.0f + v;
    float num = __fmaf_rn(u * hp, t2, 1.0f - v);
    float den = (1.0f + u) * t2;
    return __fdividef(num, den);
}

// ---------------- prep ----------------
__global__ void prep_kernel(const float* __restrict__ x) {
    __shared__ float s[In][65];
    const int t = blockIdx.x;
    const int tid = threadIdx.x;
    for (int idx = tid; idx < Bn * In; idx += PT) {
        int b = idx >> 7, i = idx & (In - 1);
        s[i][b] = x[((size_t)b * Tn + t) * In + i];
    }
    __syncthreads();
    for (int idx = tid; idx < In * Bn; idx += PT) {
        int i = idx >> 6, b = idx & (Bn - 1);
        g_xT2[((size_t)t * In + i) * Bn + b] = dup2(s[i][b]);
    }
    if (t == 0 && tid < NBG) { g_ctrA[tid * 32] = 0u; g_ctrB[tid * 32] = 0u; }
    if (t < 2) {
        for (int i = tid; i < Hn * Bn; i += PT) {
            g_h0[t * Hn * Bn + i] = 0.0f;
            g_h1[t * Hn * Bn + i] = 0.0f;
        }
    }
}

// ---------------- persistent pipelined RNN kernel ----------------
__global__ void __launch_bounds__(THREADS, 1) rnn_kernel(
    const float* __restrict__ Wih0, const float* __restrict__ Whh0,
    const float* __restrict__ bh0,  const float* __restrict__ Wax0,
    const float* __restrict__ Wah0, const float* __restrict__ ba0,
    const float* __restrict__ Wih1, const float* __restrict__ Whh1,
    const float* __restrict__ bh1,  const float* __restrict__ Wax1,
    const float* __restrict__ Wah1, const float* __restrict__ ba1,
    float* __restrict__ out)
{
    extern __shared__ u64 sm[];
    u64* wAs   = sm;                       // [KA][16]
    u64* wBs   = wAs + KA * NCOL;          // [KB][16]
    u64* sh0   = wBs + KB * NCOL;          // [2][Hn][NBAT] dup'd
    u64* sh1   = sh0 + 2 * Hn * NBAT;      // [Hn][NBAT] dup'd
    u64* redA  = sh1 + Hn * NBAT;          // [256][RS]
    u64* redB  = redA + 256 * RS;          // [256][RS]
    u64* biasA = redB + 256 * RS;          // [16]
    u64* biasB = biasA + NCOL;             // [16]
    __shared__ unsigned s_aStage, s_bDone;

    const int tid  = threadIdx.x;
    const int cg   = blockIdx.x & (NCG - 1);
    const int bg   = blockIdx.x >> 4;
    const int col0 = cg * NCOL;
    const int b0g  = bg * NBAT;
    unsigned* ctrA = &g_ctrA[bg * 32];
    unsigned* ctrB = &g_ctrB[bg * 32];

    // ---- one-time gather (all 512 threads, before engine split) ----
    for (int idx = tid; idx < KA * NCOL; idx += THREADS) {
        int k = idx >> 4, c = idx & 15, C = col0 + c;
        float wc = (k < In) ? Wih0[k * Hn + C] : Whh0[(k - In) * Hn + C];
        float wa = (k < In) ? Wax0[k * Hn + C] : Wah0[(k - In) * Hn + C];
        wAs[idx] = pack2(wc, wa);
    }
    for (int idx = tid; idx < KB * NCOL; idx += THREADS) {
        int k = idx >> 4, c = idx & 15, C = col0 + c;
        float wc = (k < Hn) ? Wih1[k * Hn + C] : Whh1[(k - Hn) * Hn + C];
        float wa = (k < Hn) ? Wax1[k * Hn + C] : Wah1[(k - Hn) * Hn + C];
        wBs[idx] = pack2(wc, wa);
    }
    if (tid < NCOL) {
        biasA[tid] = pack2(bh0[col0 + tid], ba0[col0 + tid]);
        biasB[tid] = pack2(bh1[col0 + tid], ba1[col0 + tid]);
    }
    if (tid == 0) { s_aStage = 0u; s_bDone = 0u; }
    __syncthreads();   // LAST CTA-wide barrier 0

    const size_t OFF = (size_t)Bn * Tn * Hn;

    if (tid >= 256) {
        // ================= A-engine (warps 8-15: higher arbiter priority) =================
        const int atid = tid - 256;
        const int w  = atid >> 5, ln = atid & 31;
        const int bp = ln >> 3,  cp = ln & 7;
        const int b0 = b0g + bp * 2;
        const int rb = atid >> 4, rc = atid & 15;          // epilogue cell (atid<128)
        const int ridx = (rb >> 1) * 8 + (rc >> 1);
        const int raid = (rb & 1) * 2 + (rc & 1);
        const int C = col0 + rc, B = b0g + rb;
        float hprev = 0.0f;

        for (int s = 0; s <= Tn; s++) {
            const bool full = (s < Tn);
            u64 a00 = 0, a01 = 0, a10 = 0, a11 = 0;

            // x-part (independent of all syncs) — overlaps the polls below
            if (full) {
                const u64* xp = g_xT2 + ((size_t)s * In + w * 16) * Bn + b0;
                const u64* wp = wAs + (w * 16) * NCOL + cp * 2;
#pragma unroll
                for (int i = 0; i < 16; i++) {
                    u64 s0, s1; ldcg2(xp + (size_t)i * Bn, s0, s1);
                    ulonglong2 wv = *(const ulonglong2*)(wp + i * NCOL);
                    fma2(a00, s0, wv.x); fma2(a01, s0, wv.y);
                    fma2(a10, s1, wv.x); fma2(a11, s1, wv.y);
                }
            }
            s_poll(&s_bDone, s - 2);          // sh0[s&1] free (B(s-3) finished)
            g_poll(ctrA, 16 * s);             // h0[s-1] visible globally

            // stage h0[s-1]: g_h0 buf[(s+1)&1] -> sh0[s&1], dup'd
            {
                const float* src = g_h0 + ((((s + 1) & 1)) * Hn + atid) * Bn + b0g;
                float4 v0 = ldcgf4(src);
                float4 v1 = ldcgf4(src + 4);
                u64* d = sh0 + (((s & 1)) * Hn + atid) * NBAT;
                *(ulonglong2*)(d)     = make_ulonglong2(dup2(v0.x), dup2(v0.y));
                *(ulonglong2*)(d + 2) = make_ulonglong2(dup2(v0.z), dup2(v0.w));
                *(ulonglong2*)(d + 4) = make_ulonglong2(dup2(v1.x), dup2(v1.y));
                *(ulonglong2*)(d + 6) = make_ulonglong2(dup2(v1.z), dup2(v1.w));
            }
            nbar(1);
            if (atid == 0) atomicAdd_block(&s_aStage, 1u);   // publish staging (bar drained STS)

            if (full) {
                // h-part: sh0[s&1] x wAs[In..]
                const u64* sp = sh0 + (((s & 1)) * Hn + w * 32) * NBAT + bp * 2;
                const u64* wp = wAs + (In + w * 32) * NCOL + cp * 2;
#pragma unroll 8
                for (int i = 0; i < 32; i++) {
                    ulonglong2 sv = *(const ulonglong2*)(sp + i * NBAT);
                    ulonglong2 wv = *(const ulonglong2*)(wp + i * NCOL);
                    fma2(a00, sv.x, wv.x); fma2(a01, sv.x, wv.y);
                    fma2(a10, sv.y, wv.x); fma2(a11, sv.y, wv.y);
                }
                u64* rr = redA + atid * RS;
                *(ulonglong2*)(rr)     = make_ulonglong2(a00, a01);
                *(ulonglong2*)(rr + 2) = make_ulonglong2(a10, a11);
                nbar(1);
                if (atid < 128) {
                    u64 acc = biasA[rc];
#pragma unroll
                    for (int ww = 0; ww < 8; ww++)
                        acc = add2(acc, redA[(ww * 32 + ridx) * RS + raid]);
                    float hn = blend(acc, hprev);
                    hprev = hn;
                    stcgf(&g_h0[((s & 1) * Hn + C) * Bn + B], hn);
                }
                nbar(1);
                if (atid == 0) g_arrive(ctrA);
            }
        }
        if (atid < 128) out[OFF + (size_t)B * Hn + C] = hprev;

    } else {
        // ================= B-engine (warps 0-7) =================
        const int btid = tid;
        const int w  = btid >> 5, ln = btid & 31;
        const int bp = ln >> 3,  cp = ln & 7;
        const int rb = btid >> 4, rc = btid & 15;
        const int ridx = (rb >> 1) * 8 + (rc >> 1);
        const int raid = (rb & 1) * 2 + (rc & 1);
        const int C = col0 + rc, B = b0g + rb;
        float hprev = 0.0f;

        for (int t = 0; t < Tn; t++) {
            s_poll(&s_aStage, t + 2);        // h0[t] staged in sh0[(t+1)&1] by A(t+1)
            g_poll(ctrB, 16 * t);            // h1[t-1] visible globally

            // stage h1[t-1]: g_h1 buf[(t+1)&1] -> sh1
            {
                const float* src = g_h1 + ((((t + 1) & 1)) * Hn + btid) * Bn + b0g;
                float4 v0 = ldcgf4(src);
                float4 v1 = ldcgf4(src + 4);
                u64* d = sh1 + btid * NBAT;
                *(ulonglong2*)(d)     = make_ulonglong2(dup2(v0.x), dup2(v0.y));
                *(ulonglong2*)(d + 2) = make_ulonglong2(dup2(v0.z), dup2(v0.w));
                *(ulonglong2*)(d + 4) = make_ulonglong2(dup2(v1.x), dup2(v1.y));
                *(ulonglong2*)(d + 6) = make_ulonglong2(dup2(v1.z), dup2(v1.w));
            }
            nbar(2);

            u64 a00 = 0, a01 = 0, a10 = 0, a11 = 0;
            {
                const int p0 = (t + 1) & 1;
                const u64* s0 = sh0 + (p0 * Hn + w * 32) * NBAT + bp * 2;
                const u64* w1 = wBs + (w * 32) * NCOL + cp * 2;
                const u64* s1 = sh1 + (w * 32) * NBAT + bp * 2;
                const u64* w2 = wBs + (Hn + w * 32) * NCOL + cp * 2;
#pragma unroll 8
                for (int i = 0; i < 32; i++) {
                    ulonglong2 sv = *(const ulonglong2*)(s0 + i * NBAT);
                    ulonglong2 wv = *(const ulonglong2*)(w1 + i * NCOL);
                    fma2(a00, sv.x, wv.x); fma2(a01, sv.x, wv.y);
                    fma2(a10, sv.y, wv.x); fma2(a11, sv.y, wv.y);
                    sv = *(const ulonglong2*)(s1 + i * NBAT);
                    wv = *(const ulonglong2*)(w2 + i * NCOL);
                    fma2(a00, sv.x, wv.x); fma2(a01, sv.x, wv.y);
                    fma2(a10, sv.y, wv.x); fma2(a11, sv.y, wv.y);
                }
            }
            {
                u64* rr = redB + btid * RS;
                *(ulonglong2*)(rr)     = make_ulonglong2(a00, a01);
                *(ulonglong2*)(rr + 2) = make_ulonglong2(a10, a11);
            }
            nbar(2);
            if (btid == 0) atomicAdd_block(&s_bDone, 1u);    // sh0[(t+1)&1] reads done

            if (btid < 128) {
                u64 acc = biasB[rc];
#pragma unroll
                for (int ww = 0; ww < 8; ww++)
                    acc = add2(acc, redB[(ww * 32 + ridx) * RS + raid]);
                float hn = blend(acc, hprev);
                hprev = hn;
                stcgf(&g_h1[((t & 1) * Hn + C) * Bn + B], hn);
                out[((size_t)B * Tn + t) * Hn + C] = hn;
            }
            nbar(2);
            if (btid == 0) g_arrive(ctrB);
        }
        if (btid < 128) out[OFF + (size_t)Bn * Hn + (size_t)B * Hn + C] = hprev;
    }
}

// ---------------- launch ----------------
extern "C" void kernel_launch(void* const* d_in, const int* in_sizes, int n_in,
                              void* d_out, int out_size) {
    const float* x    = (const float*)d_in[0];
    const float* Wih0 = (const float*)d_in[1];
    const float* Whh0 = (const float*)d_in[2];
    const float* bh0  = (const float*)d_in[3];
    const float* Wax0 = (const float*)d_in[4];
    const float* Wah0 = (const float*)d_in[5];
    const float* ba0  = (const float*)d_in[6];
    const float* Wih1 = (const float*)d_in[7];
    const float* Whh1 = (const float*)d_in[8];
    const float* bh1  = (const float*)d_in[9];
    const float* Wax1 = (const float*)d_in[10];
    const float* Wah1 = (const float*)d_in[11];
    const float* ba1  = (const float*)d_in[12];
    float* out = (float*)d_out;

    const int smem = (KA * NCOL + KB * NCOL       // weights
                    + 2 * Hn * NBAT + Hn * NBAT   // sh0 x2 + sh1
                    + 2 * 256 * RS                // redA + redB
                    + 2 * NCOL) * 8;              // biases
    cudaFuncSetAttribute(rnn_kernel, cudaFuncAttributeMaxDynamicSharedMemorySize, smem);

    prep_kernel<<<Tn, PT>>>(x);
    rnn_kernel<<<GCTA, THREADS, smem>>>(
        Wih0, Whh0, bh0, Wax0, Wah0, ba0,
        Wih1, Whh1, bh1, Wax1, Wah1, ba1,
        out);
}